// round 14
// baseline (speedup 1.0000x reference)
#include <cuda_runtime.h>
#include <cuda_bf16.h>

// UnitarySpectralFilter — FINAL. Converged at the sm_103a HBM/LTS roofline.
//
// y = Re[ ifft( fft(x, n=4) * exp(i*alpha*atan(log(|k|+eps))) ) ]
// n=4, k=[0,.25,-.5,-.25], phi1==phi3, real input. Real-part closed form/row:
//   s02=x0+x2 ; s13=x1+x3 ; a=s02+s13 ; c=s02-s13 ; u=x0-x2 ; v=x1-x3
//   Pre=a*C0+c*C2 ; Qre=a*C0-c*C2
//   out = (Pre+u*C1, Qre+v*C1, Pre-u*C1, Qre-v*C1)
// with C0=cos(alpha*t0)/4, C2=cos(alpha*t2)/4, C1=cos(alpha*t1)/2
// (ifft 1/4 normalization and the factor-2 on H1 folded into the constants).
//
// Session evidence (kernel us / DRAM%), 6 layouts:
//   8192x256 grid-stride (R4/R11/R12, this) : 76.4-77.3 / 79.1-80.1  <- optimum
//   4096x512 grid-stride (R13)              : 76.8 / 79.7  (tied)
//   dual-stream MLP=2 (R8)                  : 76.8 / 79.9  (tied)
//   +__ldcs/__stcs (R7)                     : 79.5 / 77.3  (rejected)
//   single-wave persistent 1184 blocks (R10): 81.3 / 75.6  (rejected)
//   flat 1 row/thread (R6)                  : 86.5 / 71.1  (rejected)
// All good variants measure 6270-6350 GB/s = the path-independent LTS chip cap.
// Traffic is the algorithmic minimum (268 MB in + 268 MB out). Roofline reached.

__global__ void usf_kernel(const float4* __restrict__ in,
                           float4* __restrict__ out,
                           const float* __restrict__ alpha_p,
                           int nrows) {
    const float alpha = alpha_p ? *alpha_p : 1.0f;

    const float t0 = atanf(logf(1e-8f));
    const float t1 = atanf(logf(0.25f + 1e-8f));
    const float t2 = atanf(logf(0.5f  + 1e-8f));

    const float C0 = 0.25f * cosf(alpha * t0);
    const float C1 = 0.5f  * cosf(alpha * t1);
    const float C2 = 0.25f * cosf(alpha * t2);

    const int stride = gridDim.x * blockDim.x;
    for (int i = blockIdx.x * blockDim.x + threadIdx.x; i < nrows; i += stride) {
        float4 x = in[i];

        float s02 = x.x + x.z;
        float s13 = x.y + x.w;
        float a   = s02 + s13;
        float cc  = s02 - s13;
        float u   = x.x - x.z;
        float v   = x.y - x.w;

        float A1  = a * C0;
        float Pre = fmaf(cc,  C2, A1);
        float Qre = fmaf(cc, -C2, A1);

        float4 o;
        o.x = fmaf(u,  C1, Pre);   // y0.re
        o.y = fmaf(v,  C1, Qre);   // y1.re
        o.z = fmaf(u, -C1, Pre);   // y2.re
        o.w = fmaf(v, -C1, Qre);   // y3.re

        out[i] = o;
    }
}

extern "C" void kernel_launch(void* const* d_in, const int* in_sizes, int n_in,
                              void* d_out, int out_size) {
    // psi = largest buffer, alpha = tiny buffer (observed: n_in=2, sizes 67108864 / 1)
    int psi_idx = 0;
    for (int i = 1; i < n_in; i++)
        if (in_sizes[i] > in_sizes[psi_idx]) psi_idx = i;

    const float* alpha = nullptr;
    for (int i = 0; i < n_in; i++)
        if (i != psi_idx && d_in[i] != nullptr && in_sizes[i] >= 1 && in_sizes[i] <= 4) {
            alpha = (const float*)d_in[i];
            break;
        }

    const float4* psi = (const float4*)d_in[psi_idx];
    float4*       out = (float4*)d_out;

    const int nrows = in_sizes[psi_idx] / 4;   // 16,777,216 rows of 4 floats

    const int block = 256;
    const int grid  = 8192;                    // ~2.1M threads, ~8 rows/thread
    usf_kernel<<<grid, block>>>(psi, out, alpha, nrows);
}

// round 15
// speedup vs baseline: 1.0199x; 1.0199x over previous
#include <cuda_runtime.h>
#include <cuda_bf16.h>

// UnitarySpectralFilter — wave-count bracket probe (8192 -> 16384 blocks).
//
// y = Re[ ifft( fft(x, n=4) * exp(i*alpha*atan(log(|k|+eps))) ) ]
// n=4, k=[0,.25,-.5,-.25], phi1==phi3, real input. Real-part closed form/row:
//   s02=x0+x2 ; s13=x1+x3 ; a=s02+s13 ; c=s02-s13 ; u=x0-x2 ; v=x1-x3
//   Pre=a*C0+c*C2 ; Qre=a*C0-c*C2
//   out = (Pre+u*C1, Qre+v*C1, Pre-u*C1, Qre-v*C1)
// with C0=cos(alpha*t0)/4, C2=cos(alpha*t2)/4, C1=cos(alpha*t1)/2.
//
// Session evidence (kernel us / DRAM%):
//   8192x256, ~7 waves (R4/R11/R12/R14) : 76.4-77.3 / 79.1-80.1  <- best
//   4096x512 (R13)                      : 76.8 / 79.7  (tied)
//   dual-stream MLP=2 (R8)              : 76.8 / 79.9  (tied)
//   1184 blocks, 1 wave (R10)           : 81.3 / 75.6  (lost backfill)
// Wave count has only been probed downward; this tests upward (~14 waves,
// 4 rows/thread). All good variants sit at the 6270-6350 GB/s LTS chip cap.

__global__ void usf_kernel(const float4* __restrict__ in,
                           float4* __restrict__ out,
                           const float* __restrict__ alpha_p,
                           int nrows) {
    const float alpha = alpha_p ? *alpha_p : 1.0f;

    const float t0 = atanf(logf(1e-8f));
    const float t1 = atanf(logf(0.25f + 1e-8f));
    const float t2 = atanf(logf(0.5f  + 1e-8f));

    const float C0 = 0.25f * cosf(alpha * t0);
    const float C1 = 0.5f  * cosf(alpha * t1);
    const float C2 = 0.25f * cosf(alpha * t2);

    const int stride = gridDim.x * blockDim.x;   // 4,194,304 threads
    for (int i = blockIdx.x * blockDim.x + threadIdx.x; i < nrows; i += stride) {
        float4 x = in[i];

        float s02 = x.x + x.z;
        float s13 = x.y + x.w;
        float a   = s02 + s13;
        float cc  = s02 - s13;
        float u   = x.x - x.z;
        float v   = x.y - x.w;

        float A1  = a * C0;
        float Pre = fmaf(cc,  C2, A1);
        float Qre = fmaf(cc, -C2, A1);

        float4 o;
        o.x = fmaf(u,  C1, Pre);   // y0.re
        o.y = fmaf(v,  C1, Qre);   // y1.re
        o.z = fmaf(u, -C1, Pre);   // y2.re
        o.w = fmaf(v, -C1, Qre);   // y3.re

        out[i] = o;
    }
}

extern "C" void kernel_launch(void* const* d_in, const int* in_sizes, int n_in,
                              void* d_out, int out_size) {
    // psi = largest buffer, alpha = tiny buffer (observed: n_in=2, sizes 67108864 / 1)
    int psi_idx = 0;
    for (int i = 1; i < n_in; i++)
        if (in_sizes[i] > in_sizes[psi_idx]) psi_idx = i;

    const float* alpha = nullptr;
    for (int i = 0; i < n_in; i++)
        if (i != psi_idx && d_in[i] != nullptr && in_sizes[i] >= 1 && in_sizes[i] <= 4) {
            alpha = (const float*)d_in[i];
            break;
        }

    const float4* psi = (const float4*)d_in[psi_idx];
    float4*       out = (float4*)d_out;

    const int nrows = in_sizes[psi_idx] / 4;   // 16,777,216 rows of 4 floats

    const int block = 256;
    const int grid  = 16384;                   // ~4.2M threads, 4 rows/thread
    usf_kernel<<<grid, block>>>(psi, out, alpha, nrows);
}